// round 16
// baseline (speedup 1.0000x reference)
#include <cuda_runtime.h>
#include <cuda_fp16.h>
#include <math.h>

// Problem constants (ManifoldGPRFilter: N=100000, D=64, E=1000000, L=10)
#define NMAX 100000
#define EMAX 1000000
#define DIM  64
#define EPSV 1e-8f

// ---------------- static device scratch (no runtime allocation) ----------------
// g_deg is zero at module load (CUDA zero-init) and re-zeroed by the LAST
// k_spmm_renorm launch of every call -> each call sees zeros. Deterministic.
__device__ __half2 g_Xh[(size_t)NMAX * (DIM / 2)];
__device__ __half2 g_H0[(size_t)NMAX * (DIM / 2)];
__device__ __half2 g_H1[(size_t)NMAX * (DIM / 2)];
__device__ int   g_deg[NMAX];
__device__ int   g_off[NMAX + 1];
__device__ int   g_cur[NMAX];
__device__ int2  g_edge[EMAX];     // packed (src, half2(val,val) bits)
__device__ int   g_bsum[1024];

// ---------------- prep: X -> fp16, Z = w0*X, degree histogram (g_deg pre-zeroed) ----------------
__global__ void k_prep(const float* __restrict__ X, __half2* __restrict__ Xh,
                       float* __restrict__ Z, const float* __restrict__ w,
                       const int* __restrict__ dst, int n4, int e) {
    int i = blockIdx.x * blockDim.x + threadIdx.x;
    if (i < n4) {
        float w0 = __ldg(w);
        float4 x = ((const float4*)X)[i];
        Xh[i * 2]     = __floats2half2_rn(x.x, x.y);
        Xh[i * 2 + 1] = __floats2half2_rn(x.z, x.w);
        float4 z;
        z.x = w0 * x.x; z.y = w0 * x.y; z.z = w0 * x.z; z.w = w0 * x.w;
        ((float4*)Z)[i] = z;
    }
    if (i < e) atomicAdd(&g_deg[dst[i]], 1);
}

#define SCAN_B 1024
__global__ void k_scan1(int n) {
    __shared__ int sh[SCAN_B];
    int i = blockIdx.x * SCAN_B + threadIdx.x;
    int v = (i < n) ? g_deg[i] : 0;
    sh[threadIdx.x] = v;
    __syncthreads();
    for (int o = 1; o < SCAN_B; o <<= 1) {
        int t = 0;
        if (threadIdx.x >= o) t = sh[threadIdx.x - o];
        __syncthreads();
        if (threadIdx.x >= o) sh[threadIdx.x] += t;
        __syncthreads();
    }
    if (i < n) g_off[i] = sh[threadIdx.x] - v;        // exclusive within block
    if (threadIdx.x == SCAN_B - 1) g_bsum[blockIdx.x] = sh[threadIdx.x];
}

// merged scan2+scan3: each block independently sums preceding block aggregates
// (nb <= 98 values -> one warp-reduce per 256-thread block), then applies its
// prefix to its SCAN_B range of g_off and initializes g_cur.
__global__ void k_scan23(int n, int nb) {
    __shared__ int s_pre;
    int bid = blockIdx.x;
    int t = threadIdx.x;
    if (t == 0) s_pre = 0;
    __syncthreads();
    int v = (t < bid && t < nb) ? g_bsum[t] : 0;
    #pragma unroll
    for (int o = 16; o; o >>= 1) v += __shfl_down_sync(0xffffffffu, v, o);
    if ((t & 31) == 0 && v) atomicAdd(&s_pre, v);
    __syncthreads();
    int pre = s_pre;
    for (int k = t; k < SCAN_B; k += blockDim.x) {
        int i = bid * SCAN_B + k;
        if (i < n) {
            int o2 = g_off[i] + pre;
            g_off[i] = o2;
            g_cur[i] = o2;
        }
    }
    if (bid == nb - 1 && t == 0)
        g_off[n] = pre + g_bsum[bid];
}

__global__ void k_scatter(const int* __restrict__ src, const int* __restrict__ dst,
                          const float* __restrict__ val, int e) {
    int i = blockIdx.x * blockDim.x + threadIdx.x;
    if (i < e) {
        int d = dst[i];
        int pos = atomicAdd(&g_cur[d], 1);
        __half2 v2 = __floats2half2_rn(val[i], val[i]);
        g_edge[pos] = make_int2(src[i], *(const int*)&v2);
    }
}

// ---------------- fused SpMM + hyperbolic renorm + Z accumulation ----------------
// EXACT R12/R14/R15 loop (measured best): one warp per destination row, edges
// in PAIRS (lanes 0-15 even edge, 16-31 odd edge), HFMA2 accumulation,
// approx-MUFU epilogue. On the LAST level (zeroDeg=1) lane 0 re-zeroes
// g_deg[row] for the next replay.
__global__ __launch_bounds__(256)
void k_spmm_renorm(const __half2* __restrict__ Hin, __half2* __restrict__ Hout,
                   float* __restrict__ Z, const float* __restrict__ w,
                   int l, int n, int writeH, int zeroDeg) {
    int warp = (blockIdx.x * blockDim.x + threadIdx.x) >> 5;
    int lane = threadIdx.x & 31;
    if (warp >= n) return;

    int half = lane >> 4;      // parity group
    int sub  = lane & 15;      // column group: owns cols [4*sub, 4*sub+4)

    int beg = g_off[warp];
    int end = g_off[warp + 1];

    if (zeroDeg && lane == 0) g_deg[warp] = 0;

    const uint2* Hrows = reinterpret_cast<const uint2*>(Hin);

    __half2 a01 = __float2half2_rn(0.f);
    __half2 a23 = __float2half2_rn(0.f);

    int e = beg;
    // 4 edges per iteration: two independent edge-pair chains in flight
    for (; e + 4 <= end; e += 4) {
        int2 ed0 = __ldg(&g_edge[e + half]);
        int2 ed1 = __ldg(&g_edge[e + 2 + half]);
        uint2 h0 = __ldg(Hrows + (size_t)ed0.x * 16 + sub);
        uint2 h1 = __ldg(Hrows + (size_t)ed1.x * 16 + sub);
        __half2 v0 = *(const __half2*)&ed0.y;
        __half2 v1 = *(const __half2*)&ed1.y;
        a01 = __hfma2(v0, *(const __half2*)&h0.x, a01);
        a23 = __hfma2(v0, *(const __half2*)&h0.y, a23);
        a01 = __hfma2(v1, *(const __half2*)&h1.x, a01);
        a23 = __hfma2(v1, *(const __half2*)&h1.y, a23);
    }
    // remaining pair
    if (e + 2 <= end) {
        int2 ed = __ldg(&g_edge[e + half]);
        uint2 h = __ldg(Hrows + (size_t)ed.x * 16 + sub);
        __half2 v = *(const __half2*)&ed.y;
        a01 = __hfma2(v, *(const __half2*)&h.x, a01);
        a23 = __hfma2(v, *(const __half2*)&h.y, a23);
        e += 2;
    }
    // odd tail: only parity-0 lanes process
    if (e < end && half == 0) {
        int2 ed = __ldg(&g_edge[e]);
        uint2 h = __ldg(Hrows + (size_t)ed.x * 16 + sub);
        __half2 v = *(const __half2*)&ed.y;
        a01 = __hfma2(v, *(const __half2*)&h.x, a01);
        a23 = __hfma2(v, *(const __half2*)&h.y, a23);
    }

    // to float for reduction / renorm
    float2 f01 = __half22float2(a01);
    float2 f23 = __half22float2(a23);
    float ax = f01.x, ay = f01.y, az = f23.x, aw = f23.y;

    // merge parity halves: lane s += lane s+16
    ax += __shfl_down_sync(0xffffffffu, ax, 16);
    ay += __shfl_down_sync(0xffffffffu, ay, 16);
    az += __shfl_down_sync(0xffffffffu, az, 16);
    aw += __shfl_down_sync(0xffffffffu, aw, 16);

    // row norm: reduce within lanes 0-15
    float ss = ax * ax + ay * ay + az * az + aw * aw;
    #pragma unroll
    for (int o = 8; o; o >>= 1) ss += __shfl_xor_sync(0xffffffffu, ss, o);

    if (half == 0) {
        // nrm = sqrt(ss) + eps; scale = tanh(nrm) / nrm  -- all approx MUFU ops
        float nrm;
        asm("sqrt.approx.f32 %0, %1;" : "=f"(nrm) : "f"(ss));
        nrm += EPSV;
        float th, rn;
        asm("tanh.approx.f32 %0, %1;" : "=f"(th) : "f"(nrm));
        asm("rcp.approx.f32 %0, %1;"  : "=f"(rn) : "f"(nrm));
        float scale = th * rn;
        float wl    = __ldg(w + l);

        float h0 = ax * scale;
        float h1 = ay * scale;
        float h2 = az * scale;
        float h3 = aw * scale;

        if (writeH) {
            uint2 hv;
            __half2 p01 = __floats2half2_rn(h0, h1);
            __half2 p23 = __floats2half2_rn(h2, h3);
            hv.x = *(const unsigned*)&p01;
            hv.y = *(const unsigned*)&p23;
            reinterpret_cast<uint2*>(Hout)[(size_t)warp * 16 + sub] = hv;
        }

        float4* zp = reinterpret_cast<float4*>(Z + (size_t)warp * DIM) + sub;
        float4 z = *zp;
        z.x += wl * h0;
        z.y += wl * h1;
        z.z += wl * h2;
        z.w += wl * h3;
        *zp = z;
    }
}

// ---------------- launch ----------------
extern "C" void kernel_launch(void* const* d_in, const int* in_sizes, int n_in,
                              void* d_out, int out_size) {
    const float* X    = (const float*)d_in[0];
    const float* vals = (const float*)d_in[1];
    const float* w    = (const float*)d_in[2];
    const int*   src  = (const int*)d_in[3];
    const int*   dst  = (const int*)d_in[4];
    float* Z = (float*)d_out;

    int n = in_sizes[0] / DIM;
    int e = in_sizes[1];
    int L = in_sizes[2] - 1;

    __half2* xh; __half2* h0; __half2* h1;
    cudaGetSymbolAddress((void**)&xh, g_Xh);
    cudaGetSymbolAddress((void**)&h0, g_H0);
    cudaGetSymbolAddress((void**)&h1, g_H1);

    int n4 = n * DIM / 4;
    int nb = (n + SCAN_B - 1) / SCAN_B;

    // ---- prep + histogram fused (g_deg zeroed by previous call's last SpMM;
    //      zero at module load on the first call) ----
    int pthreads = (n4 > e) ? n4 : e;
    k_prep<<<(pthreads + 255) / 256, 256>>>(X, xh, Z, w, dst, n4, e);
    // ---- CSR build ----
    k_scan1<<<nb, SCAN_B>>>(n);
    k_scan23<<<nb, 256>>>(n, nb);
    k_scatter<<<(e + 255) / 256, 256>>>(src, dst, vals, e);

    // ---- L propagation steps (ping-pong fp16 H buffers, fused Z) ----
    int blocks = (n * 32 + 255) / 256;
    for (int l = 1; l <= L; l++) {
        const __half2* Hin = (l == 1) ? xh : ((l & 1) ? h1 : h0);
        __half2* Hout      = ((l & 1) ? h0 : h1);
        int writeH  = (l < L) ? 1 : 0;
        int zeroDeg = (l == L) ? 1 : 0;
        k_spmm_renorm<<<blocks, 256>>>(Hin, Hout, Z, w, l, n, writeH, zeroDeg);
    }
}

// round 17
// speedup vs baseline: 1.0433x; 1.0433x over previous
#include <cuda_runtime.h>
#include <cuda_fp16.h>
#include <math.h>

// Problem constants (ManifoldGPRFilter: N=100000, D=64, E=1000000, L=10)
#define NMAX 100000
#define EMAX 1000000
#define DIM  64
#define EPSV 1e-8f

// ---------------- static device scratch (no runtime allocation) ----------------
__device__ __half2 g_Xh[(size_t)NMAX * (DIM / 2)];
__device__ __half2 g_H0[(size_t)NMAX * (DIM / 2)];
__device__ __half2 g_H1[(size_t)NMAX * (DIM / 2)];
__device__ int   g_deg[NMAX];
__device__ int   g_off[NMAX + 1];
__device__ int   g_rank[EMAX];     // edge's rank within its dst segment
__device__ int2  g_edge[EMAX];     // packed (src, half2(val,val) bits)
__device__ int   g_bsum[1024];

// ---------------- prep: zero deg, X -> fp16, Z = w0 * X ----------------
__global__ void k_prep(const float* __restrict__ X, __half2* __restrict__ Xh,
                       float* __restrict__ Z, const float* __restrict__ w,
                       int n, int n4) {
    int i = blockIdx.x * blockDim.x + threadIdx.x;
    if (i < n) g_deg[i] = 0;
    if (i < n4) {
        float w0 = __ldg(w);
        float4 x = ((const float4*)X)[i];
        Xh[i * 2]     = __floats2half2_rn(x.x, x.y);
        Xh[i * 2 + 1] = __floats2half2_rn(x.z, x.w);
        float4 z;
        z.x = w0 * x.x; z.y = w0 * x.y; z.z = w0 * x.z; z.w = w0 * x.w;
        ((float4*)Z)[i] = z;
    }
}

// histogram + rank capture: the atomic's return value IS the edge's rank
__global__ void k_hist(const int* __restrict__ dst, int e) {
    int i = blockIdx.x * blockDim.x + threadIdx.x;
    if (i < e) {
        int r = atomicAdd(&g_deg[dst[i]], 1);
        g_rank[i] = r;
    }
}

#define SCAN_B 1024
__global__ void k_scan1(int n) {
    __shared__ int sh[SCAN_B];
    int i = blockIdx.x * SCAN_B + threadIdx.x;
    int v = (i < n) ? g_deg[i] : 0;
    sh[threadIdx.x] = v;
    __syncthreads();
    for (int o = 1; o < SCAN_B; o <<= 1) {
        int t = 0;
        if (threadIdx.x >= o) t = sh[threadIdx.x - o];
        __syncthreads();
        if (threadIdx.x >= o) sh[threadIdx.x] += t;
        __syncthreads();
    }
    if (i < n) g_off[i] = sh[threadIdx.x] - v;        // exclusive within block
    if (threadIdx.x == SCAN_B - 1) g_bsum[blockIdx.x] = sh[threadIdx.x];
}

// merged scan2+scan3: each block independently sums preceding block aggregates
// (nb <= 98 values -> one warp-reduce), then applies its prefix to its range.
__global__ void k_scan23(int n, int nb) {
    __shared__ int s_pre;
    int bid = blockIdx.x;
    int t = threadIdx.x;
    if (t == 0) s_pre = 0;
    __syncthreads();
    int v = (t < bid && t < nb) ? g_bsum[t] : 0;
    #pragma unroll
    for (int o = 16; o; o >>= 1) v += __shfl_down_sync(0xffffffffu, v, o);
    if ((t & 31) == 0 && v) atomicAdd(&s_pre, v);
    __syncthreads();
    int pre = s_pre;
    for (int k = t; k < SCAN_B; k += blockDim.x) {
        int i = bid * SCAN_B + k;
        if (i < n) g_off[i] += pre;
    }
    if (bid == nb - 1 && t == 0)
        g_off[n] = pre + g_bsum[bid];
}

// scatter: NO atomics — slot = g_off[dst] + precomputed rank
__global__ void k_scatter(const int* __restrict__ src, const int* __restrict__ dst,
                          const float* __restrict__ val, int e) {
    int i = blockIdx.x * blockDim.x + threadIdx.x;
    if (i < e) {
        int d = dst[i];
        int slot = __ldg(&g_off[d]) + g_rank[i];
        __half2 v2 = __floats2half2_rn(val[i], val[i]);
        g_edge[slot] = make_int2(src[i], *(const int*)&v2);
    }
}

// ---------------- fused SpMM + hyperbolic renorm + Z accumulation ----------------
// EXACT R12/R14/R15 loop (measured best): one warp per destination row, edges
// in PAIRS (lanes 0-15 even edge, 16-31 odd edge), HFMA2 accumulation,
// approx-MUFU epilogue.
__global__ __launch_bounds__(256)
void k_spmm_renorm(const __half2* __restrict__ Hin, __half2* __restrict__ Hout,
                   float* __restrict__ Z, const float* __restrict__ w,
                   int l, int n, int writeH) {
    int warp = (blockIdx.x * blockDim.x + threadIdx.x) >> 5;
    int lane = threadIdx.x & 31;
    if (warp >= n) return;

    int half = lane >> 4;      // parity group
    int sub  = lane & 15;      // column group: owns cols [4*sub, 4*sub+4)

    int beg = g_off[warp];
    int end = g_off[warp + 1];

    const uint2* Hrows = reinterpret_cast<const uint2*>(Hin);

    __half2 a01 = __float2half2_rn(0.f);
    __half2 a23 = __float2half2_rn(0.f);

    int e = beg;
    // 4 edges per iteration: two independent edge-pair chains in flight
    for (; e + 4 <= end; e += 4) {
        int2 ed0 = __ldg(&g_edge[e + half]);
        int2 ed1 = __ldg(&g_edge[e + 2 + half]);
        uint2 h0 = __ldg(Hrows + (size_t)ed0.x * 16 + sub);
        uint2 h1 = __ldg(Hrows + (size_t)ed1.x * 16 + sub);
        __half2 v0 = *(const __half2*)&ed0.y;
        __half2 v1 = *(const __half2*)&ed1.y;
        a01 = __hfma2(v0, *(const __half2*)&h0.x, a01);
        a23 = __hfma2(v0, *(const __half2*)&h0.y, a23);
        a01 = __hfma2(v1, *(const __half2*)&h1.x, a01);
        a23 = __hfma2(v1, *(const __half2*)&h1.y, a23);
    }
    // remaining pair
    if (e + 2 <= end) {
        int2 ed = __ldg(&g_edge[e + half]);
        uint2 h = __ldg(Hrows + (size_t)ed.x * 16 + sub);
        __half2 v = *(const __half2*)&ed.y;
        a01 = __hfma2(v, *(const __half2*)&h.x, a01);
        a23 = __hfma2(v, *(const __half2*)&h.y, a23);
        e += 2;
    }
    // odd tail: only parity-0 lanes process
    if (e < end && half == 0) {
        int2 ed = __ldg(&g_edge[e]);
        uint2 h = __ldg(Hrows + (size_t)ed.x * 16 + sub);
        __half2 v = *(const __half2*)&ed.y;
        a01 = __hfma2(v, *(const __half2*)&h.x, a01);
        a23 = __hfma2(v, *(const __half2*)&h.y, a23);
    }

    // to float for reduction / renorm
    float2 f01 = __half22float2(a01);
    float2 f23 = __half22float2(a23);
    float ax = f01.x, ay = f01.y, az = f23.x, aw = f23.y;

    // merge parity halves: lane s += lane s+16
    ax += __shfl_down_sync(0xffffffffu, ax, 16);
    ay += __shfl_down_sync(0xffffffffu, ay, 16);
    az += __shfl_down_sync(0xffffffffu, az, 16);
    aw += __shfl_down_sync(0xffffffffu, aw, 16);

    // row norm: reduce within lanes 0-15
    float ss = ax * ax + ay * ay + az * az + aw * aw;
    #pragma unroll
    for (int o = 8; o; o >>= 1) ss += __shfl_xor_sync(0xffffffffu, ss, o);

    if (half == 0) {
        // nrm = sqrt(ss) + eps; scale = tanh(nrm) / nrm  -- all approx MUFU ops
        float nrm;
        asm("sqrt.approx.f32 %0, %1;" : "=f"(nrm) : "f"(ss));
        nrm += EPSV;
        float th, rn;
        asm("tanh.approx.f32 %0, %1;" : "=f"(th) : "f"(nrm));
        asm("rcp.approx.f32 %0, %1;"  : "=f"(rn) : "f"(nrm));
        float scale = th * rn;
        float wl    = __ldg(w + l);

        float h0 = ax * scale;
        float h1 = ay * scale;
        float h2 = az * scale;
        float h3 = aw * scale;

        if (writeH) {
            uint2 hv;
            __half2 p01 = __floats2half2_rn(h0, h1);
            __half2 p23 = __floats2half2_rn(h2, h3);
            hv.x = *(const unsigned*)&p01;
            hv.y = *(const unsigned*)&p23;
            reinterpret_cast<uint2*>(Hout)[(size_t)warp * 16 + sub] = hv;
        }

        float4* zp = reinterpret_cast<float4*>(Z + (size_t)warp * DIM) + sub;
        float4 z = *zp;
        z.x += wl * h0;
        z.y += wl * h1;
        z.z += wl * h2;
        z.w += wl * h3;
        *zp = z;
    }
}

// ---------------- launch ----------------
extern "C" void kernel_launch(void* const* d_in, const int* in_sizes, int n_in,
                              void* d_out, int out_size) {
    const float* X    = (const float*)d_in[0];
    const float* vals = (const float*)d_in[1];
    const float* w    = (const float*)d_in[2];
    const int*   src  = (const int*)d_in[3];
    const int*   dst  = (const int*)d_in[4];
    float* Z = (float*)d_out;

    int n = in_sizes[0] / DIM;
    int e = in_sizes[1];
    int L = in_sizes[2] - 1;

    __half2* xh; __half2* h0; __half2* h1;
    cudaGetSymbolAddress((void**)&xh, g_Xh);
    cudaGetSymbolAddress((void**)&h0, g_H0);
    cudaGetSymbolAddress((void**)&h1, g_H1);

    int n4 = n * DIM / 4;
    int nb = (n + SCAN_B - 1) / SCAN_B;

    // ---- prep: zero deg, X->fp16, Z = w0*X ----
    k_prep<<<(n4 + 255) / 256, 256>>>(X, xh, Z, w, n, n4);
    // ---- CSR build (rank-in-histogram, atomic-free scatter) ----
    k_hist<<<(e + 255) / 256, 256>>>(dst, e);
    k_scan1<<<nb, SCAN_B>>>(n);
    k_scan23<<<nb, 256>>>(n, nb);
    k_scatter<<<(e + 255) / 256, 256>>>(src, dst, vals, e);

    // ---- L propagation steps (ping-pong fp16 H buffers, fused Z) ----
    int blocks = (n * 32 + 255) / 256;
    for (int l = 1; l <= L; l++) {
        const __half2* Hin = (l == 1) ? xh : ((l & 1) ? h1 : h0);
        __half2* Hout      = ((l & 1) ? h0 : h1);
        int writeH = (l < L) ? 1 : 0;
        k_spmm_renorm<<<blocks, 256>>>(Hin, Hout, Z, w, l, n, writeH);
    }
}